// round 3
// baseline (speedup 1.0000x reference)
#include <cuda_runtime.h>
#include <cstdint>

#define B_ 4
#define N_ 8192
#define D_ 16
#define MIN_PTS_ 10

#define TPB 128          // threads per block
#define QPT 4            // queries per thread (2 packed f32x2 accumulators)
#define QT (TPB * QPT)   // 512 queries per block
#define CSPLIT 16        // candidate splits across grid.z
#define CPB (N_ / CSPLIT) // 512 candidates per block
#define TC 128           // candidate tile staged in smem

// Partial neighbor counts per candidate-split. Fully rewritten every launch.
__device__ int g_partial[CSPLIT][B_ * N_];

__device__ __forceinline__ unsigned long long pack2(float lo, float hi) {
    unsigned long long r;
    asm("mov.b64 %0, {%1, %2};" : "=l"(r) : "f"(lo), "f"(hi));
    return r;
}
__device__ __forceinline__ void unpack2(unsigned long long v, float& lo, float& hi) {
    asm("mov.b64 {%0, %1}, %2;" : "=f"(lo), "=f"(hi) : "l"(v));
}
// Packed dual fp32 FMA (sm_100+): two independent fma chains per instruction.
__device__ __forceinline__ unsigned long long fma2(unsigned long long a,
                                                   unsigned long long b,
                                                   unsigned long long c) {
    unsigned long long r;
    asm("fma.rn.f32x2 %0, %1, %2, %3;" : "=l"(r) : "l"(a), "l"(b), "l"(c));
    return r;
}

__global__ __launch_bounds__(TPB)
void dbscan_count_kernel(const float* __restrict__ pf) {
    const int b     = blockIdx.y;
    const int qbase = blockIdx.x * QT;
    const int cbase = blockIdx.z * CPB;
    const float* X  = pf + (size_t)b * N_ * D_;
    const int tid   = threadIdx.x;

    // ---- Load QPT query rows into registers, compute h_i = 0.5*||q||^2 ----
    float h[QPT];
    float q[QPT][D_];
    #pragma unroll
    for (int r = 0; r < QPT; r++) {
        const int i = qbase + r * TPB + tid;
        const float4* row = (const float4*)(X + (size_t)i * D_);
        float4 v0 = row[0], v1 = row[1], v2 = row[2], v3 = row[3];
        q[r][0]=v0.x;  q[r][1]=v0.y;  q[r][2]=v0.z;  q[r][3]=v0.w;
        q[r][4]=v1.x;  q[r][5]=v1.y;  q[r][6]=v1.z;  q[r][7]=v1.w;
        q[r][8]=v2.x;  q[r][9]=v2.y;  q[r][10]=v2.z; q[r][11]=v2.w;
        q[r][12]=v3.x; q[r][13]=v3.y; q[r][14]=v3.z; q[r][15]=v3.w;
        float s = 0.0f;
        #pragma unroll
        for (int k = 0; k < D_; k++) s = fmaf(q[r][k], q[r][k], s);
        h[r] = 0.5f * s;
    }

    // Pack queries: qp[0][k] = (q0[k], q1[k]); qp[1][k] = (q2[k], q3[k])
    unsigned long long qp[2][D_];
    #pragma unroll
    for (int k = 0; k < D_; k++) {
        qp[0][k] = pack2(q[0][k], q[1][k]);
        qp[1][k] = pack2(q[2][k], q[3][k]);
    }

    // Candidate tile: each dim stored duplicated (c,c) so one LDS.128 feeds
    // two packed FMAs with zero repacking movs.
    __shared__ float4 sdup[TC][8];   // 16 KB
    __shared__ float  stj[TC];       // t_j = 0.5*||c||^2 - 0.125

    int cnt[QPT] = {0, 0, 0, 0};

    const int ntiles = CPB / TC;     // 4
    for (int t = 0; t < ntiles; t++) {
        __syncthreads();
        {
            const int j = cbase + t * TC + tid;   // TPB == TC
            const float4* crow = (const float4*)(X + (size_t)j * D_);
            float4 c0 = crow[0], c1 = crow[1], c2 = crow[2], c3 = crow[3];
            float s = 0.0f;
            s = fmaf(c0.x,c0.x,s); s = fmaf(c0.y,c0.y,s); s = fmaf(c0.z,c0.z,s); s = fmaf(c0.w,c0.w,s);
            s = fmaf(c1.x,c1.x,s); s = fmaf(c1.y,c1.y,s); s = fmaf(c1.z,c1.z,s); s = fmaf(c1.w,c1.w,s);
            s = fmaf(c2.x,c2.x,s); s = fmaf(c2.y,c2.y,s); s = fmaf(c2.z,c2.z,s); s = fmaf(c2.w,c2.w,s);
            s = fmaf(c3.x,c3.x,s); s = fmaf(c3.y,c3.y,s); s = fmaf(c3.z,c3.z,s); s = fmaf(c3.w,c3.w,s);
            stj[tid] = 0.5f * s - 0.125f;
            sdup[tid][0] = make_float4(c0.x, c0.x, c0.y, c0.y);
            sdup[tid][1] = make_float4(c0.z, c0.z, c0.w, c0.w);
            sdup[tid][2] = make_float4(c1.x, c1.x, c1.y, c1.y);
            sdup[tid][3] = make_float4(c1.z, c1.z, c1.w, c1.w);
            sdup[tid][4] = make_float4(c2.x, c2.x, c2.y, c2.y);
            sdup[tid][5] = make_float4(c2.z, c2.z, c2.w, c2.w);
            sdup[tid][6] = make_float4(c3.x, c3.x, c3.y, c3.y);
            sdup[tid][7] = make_float4(c3.z, c3.z, c3.w, c3.w);
        }
        __syncthreads();

        #pragma unroll 2
        for (int j = 0; j < TC; j++) {
            unsigned long long a0 = 0ull, a1 = 0ull;
            #pragma unroll
            for (int e = 0; e < 8; e++) {
                double2 cd = *reinterpret_cast<const double2*>(&sdup[j][e]);
                unsigned long long ca = __double_as_longlong(cd.x); // (c_{2e},   c_{2e})
                unsigned long long cb = __double_as_longlong(cd.y); // (c_{2e+1}, c_{2e+1})
                a0 = fma2(qp[0][2*e],     ca, a0);
                a1 = fma2(qp[1][2*e],     ca, a1);
                a0 = fma2(qp[0][2*e + 1], cb, a0);
                a1 = fma2(qp[1][2*e + 1], cb, a1);
            }
            const float tj = stj[j];
            float d00, d01, d10, d11;
            unpack2(a0, d00, d01);
            unpack2(a1, d10, d11);
            cnt[0] += (d00 > h[0] + tj);
            cnt[1] += (d01 > h[1] + tj);
            cnt[2] += (d10 > h[2] + tj);
            cnt[3] += (d11 > h[3] + tj);
        }
    }

    int* part = g_partial[blockIdx.z];
    #pragma unroll
    for (int r = 0; r < QPT; r++) {
        part[b * N_ + qbase + r * TPB + tid] = cnt[r];
    }
}

// Output written as FLOAT: the harness compares d_out as float32 (int -1 bit
// pattern 0xFFFFFFFF reinterpreted as f32 is NaN -> the round-2 nan rel_err).
__global__ void dbscan_reduce_kernel(float* __restrict__ out) {
    const int idx = blockIdx.x * blockDim.x + threadIdx.x;
    if (idx < B_ * N_) {
        int s = 0;
        #pragma unroll
        for (int z = 0; z < CSPLIT; z++) s += g_partial[z][idx];
        out[idx] = (s < MIN_PTS_) ? -1.0f : 0.0f;
    }
}

extern "C" void kernel_launch(void* const* d_in, const int* in_sizes, int n_in,
                              void* d_out, int out_size) {
    const float* pf = (const float*)d_in[0];
    float* out = (float*)d_out;
    (void)in_sizes; (void)n_in; (void)out_size;

    dim3 grid(N_ / QT, B_, CSPLIT);   // 16 x 4 x 16 = 1024 blocks
    dbscan_count_kernel<<<grid, TPB>>>(pf);
    dbscan_reduce_kernel<<<(B_ * N_ + 255) / 256, 256>>>(out);
}

// round 7
// speedup vs baseline: 2.3671x; 2.3671x over previous
#include <cuda_runtime.h>
#include <cuda_bf16.h>
#include <cstdint>

#define B_ 4
#define N_ 8192
#define D_ 16
#define MIN_PTS_ 10

#define TPB 128                 // 4 warps
#define QW 16                   // queries per warp (MMA M)
#define QCTA 64                 // queries per CTA
#define CSPLIT 2                // candidate splits across grid.z
#define CPC (N_ / CSPLIT)       // 4096 candidates per CTA
#define CT 128                  // candidate tile in smem
#define CTILES (CPC / CT)       // 32
#define NT 16                   // 8-col n-subtiles per ctile
#define SCSTRIDE 12             // words per candidate row in smem (conflict-free)

__device__ int g_partial[CSPLIT][B_ * N_];

__device__ __forceinline__ uint32_t bf16x2(float lo, float hi) {
    __nv_bfloat162 v = __floats2bfloat162_rn(lo, hi);   // .x = lo (low half)
    return *reinterpret_cast<uint32_t*>(&v);
}

__device__ __forceinline__ void mma16816(float d[4], const uint32_t a[4],
                                         uint32_t b0, uint32_t b1) {
    asm volatile(
        "mma.sync.aligned.m16n8k16.row.col.f32.bf16.bf16.f32 "
        "{%0,%1,%2,%3}, {%4,%5,%6,%7}, {%8,%9}, {%0,%1,%2,%3};"
        : "+f"(d[0]), "+f"(d[1]), "+f"(d[2]), "+f"(d[3])
        : "r"(a[0]), "r"(a[1]), "r"(a[2]), "r"(a[3]), "r"(b0), "r"(b1));
}

__global__ __launch_bounds__(TPB)
void dbscan_hmma_kernel(const float* __restrict__ pf) {
    __shared__ uint32_t scu[CT * SCSTRIDE];     // candidate tile, bf16x2 packed (6 KB)
    __shared__ float sq[QCTA][17];              // query staging (4.25 KB)

    const int tid   = threadIdx.x;
    const int warp  = tid >> 5;
    const int lane  = tid & 31;
    const int g     = lane >> 2;                // 0..7
    const int tg    = lane & 3;                 // 0..3
    const int b     = blockIdx.y;
    const int qbase = blockIdx.x * QCTA;
    const int cbase = blockIdx.z * CPC;
    const float* X  = pf + (size_t)b * N_ * D_;

    // ---- Stage queries into smem ----
    for (int i = tid; i < QCTA * 4; i += TPB) {
        const int r = i >> 2, c4 = i & 3;
        float4 v = ((const float4*)(X + (size_t)(qbase + r) * D_))[c4];
        sq[r][c4 * 4 + 0] = v.x; sq[r][c4 * 4 + 1] = v.y;
        sq[r][c4 * 4 + 2] = v.z; sq[r][c4 * 4 + 3] = v.w;
    }
    __syncthreads();

    // ---- Build A fragments (fixed for whole kernel) ----
    const int qr0 = warp * QW + g;          // local query rows
    const int qr1 = qr0 + 8;
    float h0 = 0.f, h1 = 0.f;
    #pragma unroll
    for (int k = 0; k < D_; k++) { h0 = fmaf(sq[qr0][k], sq[qr0][k], h0); }
    #pragma unroll
    for (int k = 0; k < D_; k++) { h1 = fmaf(sq[qr1][k], sq[qr1][k], h1); }
    h0 *= 0.5f; h1 *= 0.5f;

    uint32_t a[4], ae[4];
    a[0] = bf16x2(sq[qr0][2 * tg],     sq[qr0][2 * tg + 1]);
    a[1] = bf16x2(sq[qr1][2 * tg],     sq[qr1][2 * tg + 1]);
    a[2] = bf16x2(sq[qr0][2 * tg + 8], sq[qr0][2 * tg + 9]);
    a[3] = bf16x2(sq[qr1][2 * tg + 8], sq[qr1][2 * tg + 9]);
    ae[0] = (tg == 0) ? bf16x2(1.0f, h0) : 0u;   // k=16:1, k=17:h
    ae[1] = (tg == 0) ? bf16x2(1.0f, h1) : 0u;
    ae[2] = 0u; ae[3] = 0u;

    // ---- Stage candidate tile 0 ----
    {
        const float4* cr = (const float4*)(X + (size_t)(cbase + tid) * D_);
        float4 v0 = cr[0], v1 = cr[1], v2 = cr[2], v3 = cr[3];
        float s = 0.f;
        s = fmaf(v0.x,v0.x,s); s = fmaf(v0.y,v0.y,s); s = fmaf(v0.z,v0.z,s); s = fmaf(v0.w,v0.w,s);
        s = fmaf(v1.x,v1.x,s); s = fmaf(v1.y,v1.y,s); s = fmaf(v1.z,v1.z,s); s = fmaf(v1.w,v1.w,s);
        s = fmaf(v2.x,v2.x,s); s = fmaf(v2.y,v2.y,s); s = fmaf(v2.z,v2.z,s); s = fmaf(v2.w,v2.w,s);
        s = fmaf(v3.x,v3.x,s); s = fmaf(v3.y,v3.y,s); s = fmaf(v3.z,v3.z,s); s = fmaf(v3.w,v3.w,s);
        uint32_t* row = scu + tid * SCSTRIDE;
        row[0] = bf16x2(v0.x, v0.y); row[1] = bf16x2(v0.z, v0.w);
        row[2] = bf16x2(v1.x, v1.y); row[3] = bf16x2(v1.z, v1.w);
        row[4] = bf16x2(v2.x, v2.y); row[5] = bf16x2(v2.z, v2.w);
        row[6] = bf16x2(v3.x, v3.y); row[7] = bf16x2(v3.z, v3.w);
        row[8] = bf16x2(-(0.5f * s - 0.125f), -1.0f);   // k=16:-t, k=17:-1
    }
    __syncthreads();

    int cnt0 = 0, cnt1 = 0;

    for (int ct = 0; ct < CTILES; ct++) {
        const bool more = (ct + 1 < CTILES);
        // Prefetch next candidate tile into registers (overlaps compute)
        float4 nv0, nv1, nv2, nv3;
        if (more) {
            const float4* cr =
                (const float4*)(X + (size_t)(cbase + (ct + 1) * CT + tid) * D_);
            nv0 = cr[0]; nv1 = cr[1]; nv2 = cr[2]; nv3 = cr[3];
        }

        // ---- Compute: 16 n-subtiles of 8 candidates ----
        #pragma unroll 4
        for (int nt = 0; nt < NT; nt++) {
            const uint32_t* row = scu + (nt * 8 + g) * SCSTRIDE;
            uint32_t b0  = row[tg];
            uint32_t b1  = row[tg + 4];
            uint32_t be0 = (tg == 0) ? row[8] : 0u;
            float d[4] = {0.f, 0.f, 0.f, 0.f};
            mma16816(d, a,  b0,  b1);
            mma16816(d, ae, be0, 0u);
            cnt0 += (__float_as_int(d[0]) > 0);
            cnt0 += (__float_as_int(d[1]) > 0);
            cnt1 += (__float_as_int(d[2]) > 0);
            cnt1 += (__float_as_int(d[3]) > 0);
        }
        __syncthreads();   // done reading tile ct

        if (more) {
            float4 v0 = nv0, v1 = nv1, v2 = nv2, v3 = nv3;
            float s = 0.f;
            s = fmaf(v0.x,v0.x,s); s = fmaf(v0.y,v0.y,s); s = fmaf(v0.z,v0.z,s); s = fmaf(v0.w,v0.w,s);
            s = fmaf(v1.x,v1.x,s); s = fmaf(v1.y,v1.y,s); s = fmaf(v1.z,v1.z,s); s = fmaf(v1.w,v1.w,s);
            s = fmaf(v2.x,v2.x,s); s = fmaf(v2.y,v2.y,s); s = fmaf(v2.z,v2.z,s); s = fmaf(v2.w,v2.w,s);
            s = fmaf(v3.x,v3.x,s); s = fmaf(v3.y,v3.y,s); s = fmaf(v3.z,v3.z,s); s = fmaf(v3.w,v3.w,s);
            uint32_t* row = scu + tid * SCSTRIDE;
            row[0] = bf16x2(v0.x, v0.y); row[1] = bf16x2(v0.z, v0.w);
            row[2] = bf16x2(v1.x, v1.y); row[3] = bf16x2(v1.z, v1.w);
            row[4] = bf16x2(v2.x, v2.y); row[5] = bf16x2(v2.z, v2.w);
            row[6] = bf16x2(v3.x, v3.y); row[7] = bf16x2(v3.z, v3.w);
            row[8] = bf16x2(-(0.5f * s - 0.125f), -1.0f);
            __syncthreads();   // tile ct+1 ready
        }
    }

    // ---- Reduce counts across the 4 lanes of each row group ----
    cnt0 += __shfl_xor_sync(0xFFFFFFFF, cnt0, 1);
    cnt0 += __shfl_xor_sync(0xFFFFFFFF, cnt0, 2);
    cnt1 += __shfl_xor_sync(0xFFFFFFFF, cnt1, 1);
    cnt1 += __shfl_xor_sync(0xFFFFFFFF, cnt1, 2);

    if (tg == 0) {
        int* part = g_partial[blockIdx.z];
        part[b * N_ + qbase + qr0] = cnt0;
        part[b * N_ + qbase + qr1] = cnt1;
    }
}

// ---------------- reduce kernel (float output: harness compares as f32) ----------------
__global__ void dbscan_reduce_kernel(float* __restrict__ out) {
    const int idx = blockIdx.x * blockDim.x + threadIdx.x;
    if (idx < B_ * N_) {
        int s = 0;
        #pragma unroll
        for (int z = 0; z < CSPLIT; z++) s += g_partial[z][idx];
        out[idx] = (s < MIN_PTS_) ? -1.0f : 0.0f;
    }
}

extern "C" void kernel_launch(void* const* d_in, const int* in_sizes, int n_in,
                              void* d_out, int out_size) {
    const float* pf = (const float*)d_in[0];
    float* out = (float*)d_out;
    (void)in_sizes; (void)n_in; (void)out_size;

    dim3 grid(N_ / QCTA, B_, CSPLIT);   // 128 x 4 x 2 = 1024 CTAs
    dbscan_hmma_kernel<<<grid, TPB>>>(pf);
    dbscan_reduce_kernel<<<(B_ * N_ + 255) / 256, 256>>>(out);
}

// round 8
// speedup vs baseline: 2.9133x; 1.2308x over previous
#include <cuda_runtime.h>
#include <cuda_bf16.h>
#include <cstdint>

#define B_ 4
#define N_ 8192
#define D_ 16
#define MIN_PTS_ 10

#define TPB 128                 // 4 warps
#define QW 32                   // queries per warp (2 x M16 blocks)
#define QCTA 128                // queries per CTA
#define CSPLIT 4                // candidate splits across grid.z
#define CPC (N_ / CSPLIT)       // 2048 candidates per CTA
#define CT 128                  // candidate tile in smem
#define CTILES (CPC / CT)       // 16
#define NT 16                   // 8-col n-subtiles per ctile
#define SCSTRIDE 12             // words per candidate row in smem (conflict-free)

__device__ int g_partial[CSPLIT][B_ * N_];

__device__ __forceinline__ uint32_t bf16x2(float lo, float hi) {
    __nv_bfloat162 v = __floats2bfloat162_rn(lo, hi);   // .x = lo (low half)
    return *reinterpret_cast<uint32_t*>(&v);
}
__device__ __forceinline__ float rb(float x) {          // round-to-bf16 value
    return __bfloat162float(__float2bfloat16(x));
}

// D = A*B + C (C preloaded in d[])
__device__ __forceinline__ void mma16816(float d[4], const uint32_t a[4],
                                         uint32_t b0, uint32_t b1) {
    asm volatile(
        "mma.sync.aligned.m16n8k16.row.col.f32.bf16.bf16.f32 "
        "{%0,%1,%2,%3}, {%4,%5,%6,%7}, {%8,%9}, {%0,%1,%2,%3};"
        : "+f"(d[0]), "+f"(d[1]), "+f"(d[2]), "+f"(d[3])
        : "r"(a[0]), "r"(a[1]), "r"(a[2]), "r"(a[3]), "r"(b0), "r"(b1));
}

__global__ __launch_bounds__(TPB)
void dbscan_hmma_kernel(const float* __restrict__ pf) {
    __shared__ uint32_t scu[CT * SCSTRIDE];          // candidate bf16 tile (6 KB)
    __shared__ __align__(8) float snt[CT];           // -t_j = 0.125 - 0.5*||c~||^2
    __shared__ float sq[QCTA][17];                   // query staging (8.5 KB)

    const int tid   = threadIdx.x;
    const int warp  = tid >> 5;
    const int lane  = tid & 31;
    const int g     = lane >> 2;                // 0..7
    const int tg    = lane & 3;                 // 0..3
    const int b     = blockIdx.y;
    const int qbase = blockIdx.x * QCTA;
    const int cbase = blockIdx.z * CPC;
    const float* X  = pf + (size_t)b * N_ * D_;

    // ---- Stage queries (bf16-rounded values) into smem ----
    for (int i = tid; i < QCTA * 4; i += TPB) {
        const int r = i >> 2, c4 = i & 3;
        float4 v = ((const float4*)(X + (size_t)(qbase + r) * D_))[c4];
        sq[r][c4 * 4 + 0] = rb(v.x); sq[r][c4 * 4 + 1] = rb(v.y);
        sq[r][c4 * 4 + 2] = rb(v.z); sq[r][c4 * 4 + 3] = rb(v.w);
    }
    __syncthreads();

    // ---- A fragments for 2 row-blocks + nh = -(0.5*||q~||^2) ----
    const int r0 = warp * QW + g;               // rows r0, r0+8, r0+16, r0+24
    uint32_t alo[4], ahi[4];
    float nh[4];
    #pragma unroll
    for (int blk = 0; blk < 2; blk++) {
        const int ra = r0 + blk * 16, rbw = ra + 8;
        uint32_t* a = blk ? ahi : alo;
        a[0] = bf16x2(sq[ra][2 * tg],      sq[ra][2 * tg + 1]);
        a[1] = bf16x2(sq[rbw][2 * tg],     sq[rbw][2 * tg + 1]);
        a[2] = bf16x2(sq[ra][2 * tg + 8],  sq[ra][2 * tg + 9]);
        a[3] = bf16x2(sq[rbw][2 * tg + 8], sq[rbw][2 * tg + 9]);
        float s0 = 0.f, s1 = 0.f;
        #pragma unroll
        for (int k = 0; k < D_; k++) {
            s0 = fmaf(sq[ra][k], sq[ra][k], s0);
            s1 = fmaf(sq[rbw][k], sq[rbw][k], s1);
        }
        nh[blk * 2 + 0] = -0.5f * s0;
        nh[blk * 2 + 1] = -0.5f * s1;
    }

    // ---- Stage candidate tile 0 (bf16-rounded) ----
    {
        const float4* cr = (const float4*)(X + (size_t)(cbase + tid) * D_);
        float4 v0 = cr[0], v1 = cr[1], v2 = cr[2], v3 = cr[3];
        float c[16] = {rb(v0.x),rb(v0.y),rb(v0.z),rb(v0.w), rb(v1.x),rb(v1.y),rb(v1.z),rb(v1.w),
                       rb(v2.x),rb(v2.y),rb(v2.z),rb(v2.w), rb(v3.x),rb(v3.y),rb(v3.z),rb(v3.w)};
        float s = 0.f;
        #pragma unroll
        for (int k = 0; k < 16; k++) s = fmaf(c[k], c[k], s);
        uint32_t* row = scu + tid * SCSTRIDE;
        #pragma unroll
        for (int e = 0; e < 8; e++) row[e] = bf16x2(c[2 * e], c[2 * e + 1]);
        snt[tid] = 0.125f - 0.5f * s;
    }
    __syncthreads();

    int cnt[4] = {0, 0, 0, 0};

    for (int ct = 0; ct < CTILES; ct++) {
        const bool more = (ct + 1 < CTILES);
        float4 nv0, nv1, nv2, nv3;                     // prefetch next tile
        if (more) {
            const float4* cr =
                (const float4*)(X + (size_t)(cbase + (ct + 1) * CT + tid) * D_);
            nv0 = cr[0]; nv1 = cr[1]; nv2 = cr[2]; nv3 = cr[3];
        }

        #pragma unroll 4
        for (int nt = 0; nt < NT; nt++) {
            const uint32_t* row = scu + (nt * 8 + g) * SCSTRIDE;
            const uint32_t b0 = row[tg];
            const uint32_t b1 = row[tg + 4];
            const float2 ntv = *(const float2*)&snt[nt * 8 + 2 * tg];
            // C = -(h + t): sign(D) = neighbor test
            float dlo[4] = { nh[0] + ntv.x, nh[0] + ntv.y, nh[1] + ntv.x, nh[1] + ntv.y };
            float dhi[4] = { nh[2] + ntv.x, nh[2] + ntv.y, nh[3] + ntv.x, nh[3] + ntv.y };
            mma16816(dlo, alo, b0, b1);     // independent
            mma16816(dhi, ahi, b0, b1);     // independent
            cnt[0] += (__float_as_int(dlo[0]) > 0);
            cnt[0] += (__float_as_int(dlo[1]) > 0);
            cnt[1] += (__float_as_int(dlo[2]) > 0);
            cnt[1] += (__float_as_int(dlo[3]) > 0);
            cnt[2] += (__float_as_int(dhi[0]) > 0);
            cnt[2] += (__float_as_int(dhi[1]) > 0);
            cnt[3] += (__float_as_int(dhi[2]) > 0);
            cnt[3] += (__float_as_int(dhi[3]) > 0);
        }
        __syncthreads();   // done reading tile ct

        if (more) {
            float4 v0 = nv0, v1 = nv1, v2 = nv2, v3 = nv3;
            float c[16] = {rb(v0.x),rb(v0.y),rb(v0.z),rb(v0.w), rb(v1.x),rb(v1.y),rb(v1.z),rb(v1.w),
                           rb(v2.x),rb(v2.y),rb(v2.z),rb(v2.w), rb(v3.x),rb(v3.y),rb(v3.z),rb(v3.w)};
            float s = 0.f;
            #pragma unroll
            for (int k = 0; k < 16; k++) s = fmaf(c[k], c[k], s);
            uint32_t* row = scu + tid * SCSTRIDE;
            #pragma unroll
            for (int e = 0; e < 8; e++) row[e] = bf16x2(c[2 * e], c[2 * e + 1]);
            snt[tid] = 0.125f - 0.5f * s;
            __syncthreads();   // tile ct+1 ready
        }
    }

    // ---- Reduce counts across the 4 tg lanes of each row group ----
    #pragma unroll
    for (int r = 0; r < 4; r++) {
        cnt[r] += __shfl_xor_sync(0xFFFFFFFF, cnt[r], 1);
        cnt[r] += __shfl_xor_sync(0xFFFFFFFF, cnt[r], 2);
    }
    if (tg == 0) {
        int* part = g_partial[blockIdx.z];
        #pragma unroll
        for (int r = 0; r < 4; r++)
            part[b * N_ + qbase + r0 + r * 8] = cnt[r];
    }
}

// ---------------- reduce kernel (float output: harness compares as f32) ----------------
__global__ void dbscan_reduce_kernel(float* __restrict__ out) {
    const int idx = blockIdx.x * blockDim.x + threadIdx.x;
    if (idx < B_ * N_) {
        int s = 0;
        #pragma unroll
        for (int z = 0; z < CSPLIT; z++) s += g_partial[z][idx];
        out[idx] = (s < MIN_PTS_) ? -1.0f : 0.0f;
    }
}

extern "C" void kernel_launch(void* const* d_in, const int* in_sizes, int n_in,
                              void* d_out, int out_size) {
    const float* pf = (const float*)d_in[0];
    float* out = (float*)d_out;
    (void)in_sizes; (void)n_in; (void)out_size;

    dim3 grid(N_ / QCTA, B_, CSPLIT);   // 64 x 4 x 4 = 1024 CTAs
    dbscan_hmma_kernel<<<grid, TPB>>>(pf);
    dbscan_reduce_kernel<<<(B_ * N_ + 255) / 256, 256>>>(out);
}

// round 9
// speedup vs baseline: 4.0370x; 1.3857x over previous
#include <cuda_runtime.h>
#include <cuda_fp16.h>
#include <cstdint>

#define B_ 4
#define N_ 8192
#define D_ 16
#define MIN_PTS_ 10

#define TPB 128                 // 4 warps
#define QW 32                   // queries per warp (2 x M16 blocks)
#define QCTA 128                // queries per CTA
#define CSPLIT 4                // candidate splits across grid.z
#define CPC (N_ / CSPLIT)       // 2048 candidates per CTA
#define CT 128                  // candidate tile in smem
#define CTILES (CPC / CT)       // 16
#define NT 16                   // 8-col n-subtiles per ctile
#define SCSTRIDE 12             // words per candidate row in smem (conflict-free)

__device__ int g_partial[CSPLIT][B_ * N_];

__device__ __forceinline__ float rh(float x) {          // round-to-f16 value
    return __half2float(__float2half_rn(x));
}
__device__ __forceinline__ uint32_t h2u(__half2 v) { return *reinterpret_cast<uint32_t*>(&v); }
__device__ __forceinline__ __half2 u2h(uint32_t v) { return *reinterpret_cast<__half2*>(&v); }

// D = A*B + C, f16 accumulators (packed f16x2 x2)
__device__ __forceinline__ void mma16816_f16(uint32_t& d0, uint32_t& d1,
                                             const uint32_t a[4],
                                             uint32_t b0, uint32_t b1,
                                             uint32_t c0, uint32_t c1) {
    asm volatile(
        "mma.sync.aligned.m16n8k16.row.col.f16.f16.f16.f16 "
        "{%0,%1}, {%2,%3,%4,%5}, {%6,%7}, {%8,%9};"
        : "=r"(d0), "=r"(d1)
        : "r"(a[0]), "r"(a[1]), "r"(a[2]), "r"(a[3]),
          "r"(b0), "r"(b1), "r"(c0), "r"(c1));
}

__global__ __launch_bounds__(TPB)
void dbscan_hmma_kernel(const float* __restrict__ pf) {
    __shared__ uint32_t scu[CT * SCSTRIDE];          // candidate f16 tile (6 KB)
    __shared__ __align__(4) __half2 snt[CT / 2];     // packed (-t_{2m}, -t_{2m+1}) + 0.125
    __shared__ float sq[QCTA][17];                   // query staging, f16-rounded (8.5 KB)

    const int tid   = threadIdx.x;
    const int warp  = tid >> 5;
    const int lane  = tid & 31;
    const int g     = lane >> 2;                // 0..7
    const int tg    = lane & 3;                 // 0..3
    const int b     = blockIdx.y;
    const int qbase = blockIdx.x * QCTA;
    const int cbase = blockIdx.z * CPC;
    const float* X  = pf + (size_t)b * N_ * D_;

    // ---- Stage queries (f16-rounded values) into smem ----
    for (int i = tid; i < QCTA * 4; i += TPB) {
        const int r = i >> 2, c4 = i & 3;
        float4 v = ((const float4*)(X + (size_t)(qbase + r) * D_))[c4];
        sq[r][c4 * 4 + 0] = rh(v.x); sq[r][c4 * 4 + 1] = rh(v.y);
        sq[r][c4 * 4 + 2] = rh(v.z); sq[r][c4 * 4 + 3] = rh(v.w);
    }
    __syncthreads();

    // ---- A fragments (2 row-blocks) + nh pairs = (-0.5||q||^2) broadcast f16x2 ----
    const int r0 = warp * QW + g;               // rows r0, r0+8, r0+16, r0+24
    uint32_t alo[4], ahi[4], nhp[4];
    #pragma unroll
    for (int blk = 0; blk < 2; blk++) {
        const int ra = r0 + blk * 16, rbw = ra + 8;
        uint32_t* a = blk ? ahi : alo;
        a[0] = h2u(__floats2half2_rn(sq[ra][2 * tg],      sq[ra][2 * tg + 1]));
        a[1] = h2u(__floats2half2_rn(sq[rbw][2 * tg],     sq[rbw][2 * tg + 1]));
        a[2] = h2u(__floats2half2_rn(sq[ra][2 * tg + 8],  sq[ra][2 * tg + 9]));
        a[3] = h2u(__floats2half2_rn(sq[rbw][2 * tg + 8], sq[rbw][2 * tg + 9]));
        float s0 = 0.f, s1 = 0.f;
        #pragma unroll
        for (int k = 0; k < D_; k++) {
            s0 = fmaf(sq[ra][k], sq[ra][k], s0);
            s1 = fmaf(sq[rbw][k], sq[rbw][k], s1);
        }
        nhp[blk * 2 + 0] = h2u(__float2half2_rn(-0.5f * s0));
        nhp[blk * 2 + 1] = h2u(__float2half2_rn(-0.5f * s1));
    }

    // ---- Stage candidate tile 0 (f16) ----
    {
        const float4* cr = (const float4*)(X + (size_t)(cbase + tid) * D_);
        float4 v0 = cr[0], v1 = cr[1], v2 = cr[2], v3 = cr[3];
        float c[16] = {rh(v0.x),rh(v0.y),rh(v0.z),rh(v0.w), rh(v1.x),rh(v1.y),rh(v1.z),rh(v1.w),
                       rh(v2.x),rh(v2.y),rh(v2.z),rh(v2.w), rh(v3.x),rh(v3.y),rh(v3.z),rh(v3.w)};
        float s = 0.f;
        #pragma unroll
        for (int k = 0; k < 16; k++) s = fmaf(c[k], c[k], s);
        uint32_t* row = scu + tid * SCSTRIDE;
        #pragma unroll
        for (int e = 0; e < 8; e++)
            row[e] = h2u(__floats2half2_rn(c[2 * e], c[2 * e + 1]));
        // packed pair store: thread tid writes half of snt[tid/2]
        ((__half*)snt)[tid] = __float2half_rn(0.125f - 0.5f * s);
    }
    __syncthreads();

    const __half2 zero2 = __float2half2_rn(0.0f);
    __half2 acc0 = zero2, acc1 = zero2, acc2 = zero2, acc3 = zero2;

    for (int ct = 0; ct < CTILES; ct++) {
        const bool more = (ct + 1 < CTILES);
        float4 nv0, nv1, nv2, nv3;                     // prefetch next tile
        if (more) {
            const float4* cr =
                (const float4*)(X + (size_t)(cbase + (ct + 1) * CT + tid) * D_);
            nv0 = cr[0]; nv1 = cr[1]; nv2 = cr[2]; nv3 = cr[3];
        }

        #pragma unroll 4
        for (int nt = 0; nt < NT; nt++) {
            const uint32_t* row = scu + (nt * 8 + g) * SCSTRIDE;
            const uint32_t b0 = row[tg];
            const uint32_t b1 = row[tg + 4];
            const __half2 ntv = snt[nt * 4 + tg];      // cols 2tg, 2tg+1
            const uint32_t c0 = h2u(__hadd2(u2h(nhp[0]), ntv));
            const uint32_t c1 = h2u(__hadd2(u2h(nhp[1]), ntv));
            const uint32_t c2 = h2u(__hadd2(u2h(nhp[2]), ntv));
            const uint32_t c3 = h2u(__hadd2(u2h(nhp[3]), ntv));
            uint32_t d0, d1, d2, d3;
            mma16816_f16(d0, d1, alo, b0, b1, c0, c1);
            mma16816_f16(d2, d3, ahi, b0, b1, c2, c3);
            acc0 = __hadd2(acc0, __hgt2(u2h(d0), zero2));   // 1.0/0.0 per half
            acc1 = __hadd2(acc1, __hgt2(u2h(d1), zero2));
            acc2 = __hadd2(acc2, __hgt2(u2h(d2), zero2));
            acc3 = __hadd2(acc3, __hgt2(u2h(d3), zero2));
        }
        __syncthreads();   // done reading tile ct

        if (more) {
            float4 v0 = nv0, v1 = nv1, v2 = nv2, v3 = nv3;
            float c[16] = {rh(v0.x),rh(v0.y),rh(v0.z),rh(v0.w), rh(v1.x),rh(v1.y),rh(v1.z),rh(v1.w),
                           rh(v2.x),rh(v2.y),rh(v2.z),rh(v2.w), rh(v3.x),rh(v3.y),rh(v3.z),rh(v3.w)};
            float s = 0.f;
            #pragma unroll
            for (int k = 0; k < 16; k++) s = fmaf(c[k], c[k], s);
            uint32_t* row = scu + tid * SCSTRIDE;
            #pragma unroll
            for (int e = 0; e < 8; e++)
                row[e] = h2u(__floats2half2_rn(c[2 * e], c[2 * e + 1]));
            ((__half*)snt)[tid] = __float2half_rn(0.125f - 0.5f * s);
            __syncthreads();   // tile ct+1 ready
        }
    }

    // ---- Counts: halves are exact small ints in f16 ----
    int cnt[4];
    cnt[0] = (int)(__low2float(acc0) + __high2float(acc0));
    cnt[1] = (int)(__low2float(acc1) + __high2float(acc1));
    cnt[2] = (int)(__low2float(acc2) + __high2float(acc2));
    cnt[3] = (int)(__low2float(acc3) + __high2float(acc3));
    #pragma unroll
    for (int r = 0; r < 4; r++) {
        cnt[r] += __shfl_xor_sync(0xFFFFFFFF, cnt[r], 1);
        cnt[r] += __shfl_xor_sync(0xFFFFFFFF, cnt[r], 2);
    }
    if (tg == 0) {
        int* part = g_partial[blockIdx.z];
        #pragma unroll
        for (int r = 0; r < 4; r++)
            part[b * N_ + qbase + r0 + r * 8] = cnt[r];
    }
}

// ---------------- reduce kernel (float output: harness compares as f32) ----------------
__global__ void dbscan_reduce_kernel(float* __restrict__ out) {
    const int idx = blockIdx.x * blockDim.x + threadIdx.x;
    if (idx < B_ * N_) {
        int s = 0;
        #pragma unroll
        for (int z = 0; z < CSPLIT; z++) s += g_partial[z][idx];
        out[idx] = (s < MIN_PTS_) ? -1.0f : 0.0f;
    }
}

extern "C" void kernel_launch(void* const* d_in, const int* in_sizes, int n_in,
                              void* d_out, int out_size) {
    const float* pf = (const float*)d_in[0];
    float* out = (float*)d_out;
    (void)in_sizes; (void)n_in; (void)out_size;

    dim3 grid(N_ / QCTA, B_, CSPLIT);   // 64 x 4 x 4 = 1024 CTAs
    dbscan_hmma_kernel<<<grid, TPB>>>(pf);
    dbscan_reduce_kernel<<<(B_ * N_ + 255) / 256, 256>>>(out);
}